// round 16
// baseline (speedup 1.0000x reference)
#include <cuda_runtime.h>
#include <cuda_bf16.h>
#include <cuda_fp16.h>
#include <math.h>
#include <stdint.h>

#define LSEQ 4096
#define DMOD 768
#define DIN  1536
#define DST  16
#define RNK  48
#define NCOL 80
#define NCHUNK 64
#define CHLEN  64
#define INV_LM (1.0f / (4096.0f * 768.0f))

// ---------------- scratch ----------------------------------------------------
__device__ float d_wsum[DIN];
__device__ __half d_uh [LSEQ * DMOD];
__device__ __half d_wh [2 * DIN * DMOD];
__device__ __half d_xsh[LSEQ * DIN];
__device__ __half d_gh [LSEQ * DIN];     // g' = silu(z)*wsum  (INV_LM applied later)
__device__ __half d_xpwh[128 * DIN];     // padded x_proj_w (rows 80..127 = 0)
__device__ __half d_dbch[LSEQ * 64];     // dbc[:, :48] K-padded to 64
__device__ __half d_dtwh[DIN * 64];      // dt_proj_w K-padded to 64
__device__ float d_xz[LSEQ * DIN];       // x-half only (z gated in gemm1 epilogue)
__device__ float d_dt[LSEQ * DIN];
__device__ float d_dbc[LSEQ * NCOL];
#define G2_KSPLIT 16
__device__ float d_dbc_part[G2_KSPLIT][LSEQ * NCOL];
__device__ float d_P [NCHUNK * DIN * DST];
__device__ float d_E [NCHUNK * DIN * DST];
__device__ float d_Kc[NCHUNK * DIN * DST];
__device__ float d_part_conv[1536];
__device__ float d_part_scan[NCHUNK * 6];
__device__ float d_part_p2[96];

__device__ __forceinline__ float siluf(float x) { return x / (1.0f + __expf(-x)); }
__device__ __forceinline__ float softplusf(float s) {
    return (s > 20.0f) ? s : __logf(1.0f + __expf(s));
}

__device__ __forceinline__ float blockReduceSum(float v) {
    __shared__ float sh[32];
    int lane = threadIdx.x & 31;
    int w    = threadIdx.x >> 5;
    #pragma unroll
    for (int o = 16; o > 0; o >>= 1) v += __shfl_down_sync(0xffffffffu, v, o);
    if (lane == 0) sh[w] = v;
    __syncthreads();
    int nw = blockDim.x >> 5;
    v = (threadIdx.x < nw) ? sh[threadIdx.x] : 0.0f;
    if (w == 0) {
        #pragma unroll
        for (int o = 16; o > 0; o >>= 1) v += __shfl_down_sync(0xffffffffu, v, o);
    }
    return v;
}

// ---------------- asm helpers (sm_80-baseline) -------------------------------
__device__ __forceinline__ uint32_t smem_to_u32(const void* p) {
    uint32_t a;
    asm("{ .reg .u64 t; cvta.to.shared.u64 t, %1; cvt.u32.u64 %0, t; }" : "=r"(a) : "l"(p));
    return a;
}
#define CP16(sm, gp) \
    asm volatile("cp.async.cg.shared.global [%0], [%1], 16;" :: "r"(sm), "l"(gp))
#define CP_COMMIT() asm volatile("cp.async.commit_group;" ::: "memory")
#define CP_WAIT0()  asm volatile("cp.async.wait_group 0;" ::: "memory")
#define CP_WAIT1()  asm volatile("cp.async.wait_group 1;" ::: "memory")
#define CP_WAIT2()  asm volatile("cp.async.wait_group 2;" ::: "memory")

__device__ __forceinline__ void ldsm_x4(uint32_t& r0, uint32_t& r1, uint32_t& r2,
                                        uint32_t& r3, uint32_t addr) {
    asm volatile("ldmatrix.sync.aligned.m8n8.x4.shared.b16 {%0,%1,%2,%3}, [%4];"
                 : "=r"(r0), "=r"(r1), "=r"(r2), "=r"(r3) : "r"(addr));
}
__device__ __forceinline__ void mma16816(float* c, const uint32_t* a, const uint32_t* b) {
    asm volatile("mma.sync.aligned.m16n8k16.row.col.f32.f16.f16.f32 "
                 "{%0,%1,%2,%3}, {%4,%5,%6,%7}, {%8,%9}, {%0,%1,%2,%3};"
                 : "+f"(c[0]), "+f"(c[1]), "+f"(c[2]), "+f"(c[3])
                 : "r"(a[0]), "r"(a[1]), "r"(a[2]), "r"(a[3]), "r"(b[0]), "r"(b[1]));
}

// swizzled 64B-row addressing: row r, 16B slot s -> conflict-free ldmatrix
__device__ __forceinline__ uint32_t swz(uint32_t row, uint32_t slot) {
    return row * 64u + ((slot ^ ((row >> 1) & 3u)) << 4);
}

// ---------------- K_prep: patchT + wsplit + xpw pad + dtw pad + colsum -------
#define PB_PATCH  384
#define PB_WSPLIT ((2 * DIN * DMOD) / 256)       // 9216
#define PB_XPAD   ((128 * DIN) / 256)            // 768
#define PB_DTW    ((DIN * 64) / 256)             // 384
#define PB_COLSUM (DIN / 16)                     // 96
__global__ void k_prep(const float* __restrict__ x,
                       const float* __restrict__ w,
                       const float* __restrict__ xpw,
                       const float* __restrict__ dtw,
                       const float* __restrict__ opw) {
    __shared__ __half shp[8][1024];              // patchify staging (16 KB)
    int bid = blockIdx.x;
    int t = threadIdx.x;
    if (bid < PB_PATCH) {
        int c   = bid >> 7;
        int rem = bid & 127;
        int ih0 = (rem >> 4) * 8;
        int a   = rem & 15;
        #pragma unroll
        for (int rep = 0; rep < 8; rep++) {
            int j    = t + rep * 256;
            int row  = j >> 8;
            int col4 = j & 255;
            int H = (ih0 + row) * 16 + a;
            float4 v = *(const float4*)&x[c * 1048576 + H * 1024 + col4 * 4];
            shp[row][col4 * 4 + 0] = __float2half(v.x);
            shp[row][col4 * 4 + 1] = __float2half(v.y);
            shp[row][col4 * 4 + 2] = __float2half(v.z);
            shp[row][col4 * 4 + 3] = __float2half(v.w);
        }
        __syncthreads();
        int iwr = t >> 4, b = t & 15;
        int l  = iwr * 256 + a * 16 + b;
        int d0 = c * 256 + ih0 * 4;
        int colbase = iwr * 16 + b;
        uint32_t hv[16];
        #pragma unroll
        for (int j = 0; j < 16; j++) {
            int d2 = 2 * j;
            int i0 = d2 >> 2,       q0 = d2 & 3;
            int i1 = (d2 + 1) >> 2, q1 = (d2 + 1) & 3;
            __half2 hp = {shp[i0][q0 * 256 + colbase], shp[i1][q1 * 256 + colbase]};
            hv[j] = *(uint32_t*)&hp;
        }
        long base = (long)l * DMOD + d0;
        #pragma unroll
        for (int j = 0; j < 4; j++) {
            uint4 qh = {hv[4 * j], hv[4 * j + 1], hv[4 * j + 2], hv[4 * j + 3]};
            *(uint4*)&d_uh[base + j * 8] = qh;
        }
    } else if (bid < PB_PATCH + PB_WSPLIT) {
        int idx = (bid - PB_PATCH) * 256 + t;
        d_wh[idx] = __float2half(w[idx]);
    } else if (bid < PB_PATCH + PB_WSPLIT + PB_XPAD) {
        int idx = (bid - PB_PATCH - PB_WSPLIT) * 256 + t;
        int row = idx / DIN;
        d_xpwh[idx] = __float2half((row < NCOL) ? xpw[idx] : 0.0f);
    } else if (bid < PB_PATCH + PB_WSPLIT + PB_XPAD + PB_DTW) {
        int idx = (bid - PB_PATCH - PB_WSPLIT - PB_XPAD) * 256 + t;
        int row = idx >> 6;
        int k   = idx & 63;
        d_dtwh[idx] = __float2half((k < RNK) ? dtw[row * RNK + k] : 0.0f);
    } else {
        int cb = bid - PB_PATCH - PB_WSPLIT - PB_XPAD - PB_DTW;
        __shared__ float shc[16][17];
        int dl = t & 15;
        int mg = t >> 4;
        int d  = cb * 16 + dl;
        float s = 0.0f;
        for (int m = mg * 48; m < mg * 48 + 48; m++) s += opw[m * DIN + d];
        shc[dl][mg] = s;
        __syncthreads();
        if (t < 16) {
            float tot = 0.0f;
            #pragma unroll
            for (int g = 0; g < 16; g++) tot += shc[t][g];
            d_wsum[cb * 16 + t] = tot;
        }
    }
}

// ---------------- shared GEMM machinery (fp16, single term, 4-stage) ---------
#define G1_TILE   8192                  // 128 rows * 64 B
#define G1_STAGE  (2 * G1_TILE)         // A, B = 16384 B
#define G1_NSTG   4
#define G1_SMEM   (G1_NSTG * G1_STAGE)  // 65536 B
#define G1_ITERS  24                    // 768 / 32

__device__ __forceinline__ void gx_prefetch(
        uint32_t sbase, int stage, int k0, int l0, int n0, int t,
        const __half* A, const __half* B, int kstride) {
    const uint32_t so = sbase + stage * G1_STAGE;
    const int prow = t >> 2;
    const int pq   = t & 3;
    #pragma unroll
    for (int rep = 0; rep < 2; rep++) {
        int row = prow + rep * 64;
        uint32_t soff = swz((uint32_t)row, (uint32_t)pq);
        long ga = (long)(l0 + row) * kstride + k0 + pq * 8;
        long gb = (long)(n0 + row) * kstride + k0 + pq * 8;
        CP16(so + soff,           (const void*)(A + ga));
        CP16(so + G1_TILE + soff, (const void*)(B + gb));
    }
}

__device__ __forceinline__ void gx_mainloop_iter(uint32_t so, int lane, int wm, int wn,
                                                 float acc[4][4][4]) {
    #pragma unroll
    for (int kk = 0; kk < 2; kk++) {
        const uint32_t arow = (uint32_t)(wm * 64 + (lane & 15));
        const uint32_t aslot = (uint32_t)(kk * 2 + (lane >> 4));
        const int g = lane >> 3;
        const uint32_t brow = (uint32_t)(wn * 32 + ((g >> 1) << 3) + (lane & 7));
        const uint32_t bslot = (uint32_t)(kk * 2 + (g & 1));

        uint32_t af[4][4];
        #pragma unroll
        for (int mt = 0; mt < 4; mt++) {
            uint32_t addr = so + swz(arow + mt * 16, aslot);
            ldsm_x4(af[mt][0], af[mt][1], af[mt][2], af[mt][3], addr);
        }
        uint32_t bf[4][2];
        #pragma unroll
        for (int np = 0; np < 2; np++) {
            uint32_t addr = so + G1_TILE + swz(brow + np * 16, bslot);
            ldsm_x4(bf[2 * np][0], bf[2 * np][1],
                    bf[2 * np + 1][0], bf[2 * np + 1][1], addr);
        }
        #pragma unroll
        for (int mt = 0; mt < 4; mt++)
            #pragma unroll
            for (int nt = 0; nt < 4; nt++)
                mma16816(acc[mt][nt], af[mt], bf[nt]);
    }
}

// ---------------- K2: GEMM1 (x-half -> fp32 xz; z-half -> gated fp16 g') -----
__global__ void __launch_bounds__(256, 2) k_gemm1_mma() {
    extern __shared__ char smem[];
    const uint32_t sbase = smem_to_u32(smem);
    const int t    = threadIdx.x;
    const int lane = t & 31;
    const int wid  = t >> 5;
    const int wm   = wid >> 2;
    const int wn   = wid & 3;
    const int n0   = blockIdx.x * 128;
    const int l0   = blockIdx.y * 128;

    float acc[4][4][4];
    #pragma unroll
    for (int i = 0; i < 4; i++)
        #pragma unroll
        for (int j = 0; j < 4; j++)
            #pragma unroll
            for (int q = 0; q < 4; q++) acc[i][j][q] = 0.0f;

    #pragma unroll
    for (int s = 0; s < 3; s++) {
        gx_prefetch(sbase, s, s * 32, l0, n0, t, d_uh, d_wh, DMOD);
        CP_COMMIT();
    }

    for (int c = 0; c < G1_ITERS; c++) {
        CP_WAIT2();
        __syncthreads();
        if (c + 3 < G1_ITERS)
            gx_prefetch(sbase, (c + 3) % G1_NSTG, (c + 3) * 32, l0, n0, t,
                        d_uh, d_wh, DMOD);
        CP_COMMIT();
        gx_mainloop_iter(sbase + (c % G1_NSTG) * G1_STAGE, lane, wm, wn, acc);
    }

    if (n0 < DIN) {
        #pragma unroll
        for (int mt = 0; mt < 4; mt++) {
            int r0 = l0 + wm * 64 + mt * 16 + (lane >> 2);
            #pragma unroll
            for (int nt = 0; nt < 4; nt++) {
                int cc = n0 + wn * 32 + nt * 8 + 2 * (lane & 3);
                float2 v0 = {acc[mt][nt][0], acc[mt][nt][1]};
                float2 v1 = {acc[mt][nt][2], acc[mt][nt][3]};
                *(float2*)&d_xz[(long)r0 * DIN + cc]       = v0;
                *(float2*)&d_xz[(long)(r0 + 8) * DIN + cc] = v1;
            }
        }
    } else {
        // z-half: g' = silu(z) * wsum   (NO INV_LM here — fp16 subnormal hazard)
        const int zb = n0 - DIN;
        #pragma unroll
        for (int mt = 0; mt < 4; mt++) {
            int r0 = l0 + wm * 64 + mt * 16 + (lane >> 2);
            #pragma unroll
            for (int nt = 0; nt < 4; nt++) {
                int cc = zb + wn * 32 + nt * 8 + 2 * (lane & 3);
                float w0 = d_wsum[cc];
                float w1 = d_wsum[cc + 1];
                __half2 g0 = __floats2half2_rn(siluf(acc[mt][nt][0]) * w0,
                                               siluf(acc[mt][nt][1]) * w1);
                __half2 g1 = __floats2half2_rn(siluf(acc[mt][nt][2]) * w0,
                                               siluf(acc[mt][nt][3]) * w1);
                *(uint32_t*)&d_gh[(long)r0 * DIN + cc]       = *(uint32_t*)&g0;
                *(uint32_t*)&d_gh[(long)(r0 + 8) * DIN + cc] = *(uint32_t*)&g1;
            }
        }
    }
}

// -------- K3: causal depthwise conv(4) + silu, 8l x 4ch per thread -----------
__global__ void __launch_bounds__(256, 3) k_conv(const float* __restrict__ convw,
                                                 const float* __restrict__ convb,
                                                 const float* __restrict__ Dvec) {
    int idx = blockIdx.x * blockDim.x + threadIdx.x;   // (LSEQ/8)*(DIN/4)
    int lq  = idx / (DIN / 4);
    int q   = idx - lq * (DIN / 4);
    int ch0 = q * 4;
    int l0  = lq * 8;

    float4 bia = *(const float4*)&convb[ch0];
    float w4[4][4];
    #pragma unroll
    for (int j = 0; j < 4; j++) {
        float4 w = *(const float4*)&convw[(ch0 + j) * 4];
        w4[j][0] = w.x; w4[j][1] = w.y; w4[j][2] = w.z; w4[j][3] = w.w;
    }
    float4 Dv = *(const float4*)&Dvec[ch0];
    Dv.x *= INV_LM; Dv.y *= INV_LM; Dv.z *= INV_LM; Dv.w *= INV_LM;

    float4 r[11];
    #pragma unroll
    for (int k = 0; k < 11; k++) {
        int lk = l0 - 3 + k;
        if (lk >= 0) r[k] = *(const float4*)&d_xz[(long)lk * DIN + ch0];
        else         r[k] = make_float4(0.f, 0.f, 0.f, 0.f);
    }
    float local = 0.0f;
    #pragma unroll
    for (int i = 0; i < 8; i++) {
        int l = l0 + i;
        float s0 = bia.x, s1 = bia.y, s2 = bia.z, s3 = bia.w;
        #pragma unroll
        for (int k = 0; k < 4; k++) {
            float4 v = r[i + k];
            s0 += w4[0][k] * v.x;
            s1 += w4[1][k] * v.y;
            s2 += w4[2][k] * v.z;
            s3 += w4[3][k] * v.w;
        }
        float xs0 = siluf(s0), xs1 = siluf(s1), xs2 = siluf(s2), xs3 = siluf(s3);
        uint2 gvv = *(const uint2*)&d_gh[(long)l * DIN + ch0];
        float2 ga = __half22float2(*(__half2*)&gvv.x);
        float2 gb = __half22float2(*(__half2*)&gvv.y);
        __half2 hp0 = {__float2half(xs0), __float2half(xs1)};
        __half2 hp1 = {__float2half(xs2), __float2half(xs3)};
        uint2 hv = {*(uint32_t*)&hp0, *(uint32_t*)&hp1};
        *(uint2*)&d_xsh[(long)l * DIN + ch0] = hv;
        local += xs0 * Dv.x * ga.x + xs1 * Dv.y * ga.y
               + xs2 * Dv.z * gb.x + xs3 * Dv.w * gb.y;
    }
    float tot = blockReduceSum(local);
    if (threadIdx.x == 0) d_part_conv[blockIdx.x] = tot;
}

// ---------------- K4: GEMM2 via mma.sync, split-K 16 -------------------------
#define G2_KLEN  (DIN / G2_KSPLIT)     // 96
#define G2_ITERS (G2_KLEN / 32)        // 3
__global__ void __launch_bounds__(256, 2) k_gemm2_mma() {
    extern __shared__ char smem[];
    const uint32_t sbase = smem_to_u32(smem);
    const int t    = threadIdx.x;
    const int lane = t & 31;
    const int wid  = t >> 5;
    const int wm   = wid >> 2;
    const int wn   = wid & 3;
    const int l0   = blockIdx.x * 128;
    const int kz   = blockIdx.y;
    const int kbase = kz * G2_KLEN;

    float acc[4][4][4];
    #pragma unroll
    for (int i = 0; i < 4; i++)
        #pragma unroll
        for (int j = 0; j < 4; j++)
            #pragma unroll
            for (int q = 0; q < 4; q++) acc[i][j][q] = 0.0f;

    #pragma unroll
    for (int s = 0; s < 3; s++) {
        gx_prefetch(sbase, s, kbase + s * 32, l0, 0, t, d_xsh, d_xpwh, DIN);
        CP_COMMIT();
    }

    for (int c = 0; c < G2_ITERS; c++) {
        CP_WAIT2();
        __syncthreads();
        CP_COMMIT();
        gx_mainloop_iter(sbase + (c % G1_NSTG) * G1_STAGE, lane, wm, wn, acc);
    }

    #pragma unroll
    for (int mt = 0; mt < 4; mt++) {
        int r0 = l0 + wm * 64 + mt * 16 + (lane >> 2);
        #pragma unroll
        for (int nt = 0; nt < 4; nt++) {
            int cc = wn * 32 + nt * 8 + 2 * (lane & 3);
            if (cc + 1 < NCOL) {
                float2 v0 = {acc[mt][nt][0], acc[mt][nt][1]};
                float2 v1 = {acc[mt][nt][2], acc[mt][nt][3]};
                *(float2*)&d_dbc_part[kz][(long)r0 * NCOL + cc]       = v0;
                *(float2*)&d_dbc_part[kz][(long)(r0 + 8) * NCOL + cc] = v1;
            }
        }
    }
}

// ---------------- K4b: reduce split-K partials + emit dbc fp16 ---------------
__global__ void k_g2red() {
    int idx = blockIdx.x * 256 + threadIdx.x;   // < LSEQ*NCOL
    float s = 0.0f;
    #pragma unroll
    for (int kz = 0; kz < G2_KSPLIT; kz++) s += d_dbc_part[kz][idx];
    d_dbc[idx] = s;
    int l   = idx / NCOL;
    int col = idx - l * NCOL;
    if (col < RNK) {
        d_dbch[l * 64 + col] = __float2half(s);
    } else if (col >= 64) {
        d_dbch[l * 64 + col - 16] = __float2half(0.0f);
    }
}

// ---------------- K5: dt via mma.sync (M=4096, N=1536, K=48->64) -------------
__global__ void __launch_bounds__(256, 2) k_dt_mma(const float* __restrict__ dtb) {
    extern __shared__ char smem[];
    const uint32_t sbase = smem_to_u32(smem);
    const int t    = threadIdx.x;
    const int lane = t & 31;
    const int wid  = t >> 5;
    const int wm   = wid >> 2;
    const int wn   = wid & 3;
    const int l0   = blockIdx.x * 128;
    const int n0   = blockIdx.y * 128;

    float acc[4][4][4];
    #pragma unroll
    for (int i = 0; i < 4; i++)
        #pragma unroll
        for (int j = 0; j < 4; j++)
            #pragma unroll
            for (int q = 0; q < 4; q++) acc[i][j][q] = 0.0f;

    gx_prefetch(sbase, 0, 0, l0, n0, t, d_dbch, d_dtwh, 64);
    CP_COMMIT();
    gx_prefetch(sbase, 1, 32, l0, n0, t, d_dbch, d_dtwh, 64);
    CP_COMMIT();

    CP_WAIT1();
    __syncthreads();
    gx_mainloop_iter(sbase, lane, wm, wn, acc);
    CP_WAIT0();
    __syncthreads();
    gx_mainloop_iter(sbase + G1_STAGE, lane, wm, wn, acc);

    #pragma unroll
    for (int mt = 0; mt < 4; mt++) {
        int r0 = l0 + wm * 64 + mt * 16 + (lane >> 2);
        #pragma unroll
        for (int nt = 0; nt < 4; nt++) {
            int cc = n0 + wn * 32 + nt * 8 + 2 * (lane & 3);
            float b0 = dtb[cc], b1 = dtb[cc + 1];
            float2 v0 = {softplusf(acc[mt][nt][0] + b0), softplusf(acc[mt][nt][1] + b1)};
            float2 v1 = {softplusf(acc[mt][nt][2] + b0), softplusf(acc[mt][nt][3] + b1)};
            *(float2*)&d_dt[(long)r0 * DIN + cc]       = v0;
            *(float2*)&d_dt[(long)(r0 + 8) * DIN + cc] = v1;
        }
    }
}

// ---------------- K6: scan pass 1 — one thread owns 16 states of one d -------
__global__ void k_scan1(const float* __restrict__ A_log) {
    __shared__ __align__(16) float sB[CHLEN][DST];
    __shared__ __align__(16) float sC[CHLEN][DST];
    int t = threadIdx.x;
    int d = blockIdx.x * 256 + t;
    int c = blockIdx.y;
    int base = c * CHLEN;
    for (int p = t; p < CHLEN * DST; p += 256) {
        int r = p >> 4, s = p & 15;
        sB[r][s] = d_dbc[(base + r) * NCOL + RNK + s];
        sC[r][s] = d_dbc[(base + r) * NCOL + RNK + DST + s];
    }
    __syncthreads();

    float Av[DST];
    #pragma unroll
    for (int s = 0; s < DST; s++) Av[s] = -__expf(A_log[d * DST + s]);
    bool fast = true;
    #pragma unroll
    for (int s = 1; s < DST; s++) {
        float r = Av[s] / Av[0];
        fast = fast && (fabsf(r - (float)(s + 1)) < 1e-3f);
    }

    float h[DST], cp[DST], K[DST];
    #pragma unroll
    for (int s = 0; s < DST; s++) { h[s] = 0.0f; cp[s] = 1.0f; K[s] = 0.0f; }
    float acc = 0.0f;

    for (int i = 0; i < CHLEN; i++) {
        int l = base + i;
        float dtv = d_dt[(long)l * DIN + d];
        float xsv = __half2float(d_xsh[(long)l * DIN + d]);
        float gv  = __half2float(d_gh [(long)l * DIN + d]) * INV_LM;
        float dtx = dtv * xsv;
        float dAv[DST];
        if (fast) {
            float E  = __expf(dtv * Av[0]);
            float p2 = E * E, p4 = p2 * p2, p8 = p4 * p4;
            dAv[0] = E;        dAv[1] = p2;       dAv[2] = p2 * E;
            dAv[3] = p4;       dAv[4] = p4 * E;   dAv[5] = p4 * p2;
            dAv[6] = p4 * dAv[2]; dAv[7] = p8;
            dAv[8] = p8 * E;   dAv[9] = p8 * p2;  dAv[10] = p8 * dAv[2];
            dAv[11] = p8 * p4; dAv[12] = p8 * dAv[4]; dAv[13] = p8 * dAv[5];
            dAv[14] = p8 * dAv[6]; dAv[15] = p8 * p8;
        } else {
            #pragma unroll
            for (int s = 0; s < DST; s++) dAv[s] = __expf(dtv * Av[s]);
        }
        #pragma unroll
        for (int s = 0; s < DST; s++) {
            float dA = dAv[s];
            cp[s] *= dA;
            h[s] = dA * h[s] + dtx * sB[i][s];
            float cg = sC[i][s] * gv;
            acc  += h[s] * cg;
            K[s] += cp[s] * cg;
        }
    }
    long off = ((long)c * DIN + d) * DST;
    #pragma unroll
    for (int s = 0; s < DST; s++) {
        d_P [off + s] = cp[s];
        d_E [off + s] = h[s];
        d_Kc[off + s] = K[s];
    }
    float tot = blockReduceSum(acc);
    if (t == 0) d_part_scan[c * 6 + blockIdx.x] = tot;
}

// ---------------- K7: scan pass 2 (chunk combine, prefetched) ----------------
__global__ void k_scan2() {
    int gid = blockIdx.x * 256 + threadIdx.x;
    float h = 0.0f, St = 0.0f;
    float Pn = d_P[gid], En = d_E[gid], Kn = d_Kc[gid];
    for (int c = 0; c < NCHUNK; c++) {
        float Pc = Pn, Ec = En, Kk = Kn;
        if (c + 1 < NCHUNK) {
            long off = (long)(c + 1) * (DIN * DST) + gid;
            Pn = d_P[off]; En = d_E[off]; Kn = d_Kc[off];
        }
        St += Kk * h;
        h   = Pc * h + Ec;
    }
    float tot = blockReduceSum(St);
    if (threadIdx.x == 0) d_part_p2[blockIdx.x] = tot;
}

// ---------------- K8: deterministic final reduce -----------------------------
__global__ void k_final(float* __restrict__ out) {
    int t = threadIdx.x;
    float v = 0.0f;
    for (int i = t; i < 768; i += 256)           v += d_part_conv[i];
    for (int i = t; i < NCHUNK * 6; i += 256)    v += d_part_scan[i];
    for (int i = t; i < 96; i += 256)            v += d_part_p2[i];
    float tot = blockReduceSum(v);
    if (t == 0) out[0] = tot;
}

// ---------------- launch -----------------------------------------------------
extern "C" void kernel_launch(void* const* d_in, const int* in_sizes, int n_in,
                              void* d_out, int out_size) {
    const float* x     = (const float*)d_in[0];
    const float* w_in  = (const float*)d_in[1];
    const float* convw = (const float*)d_in[2];
    const float* convb = (const float*)d_in[3];
    const float* xpw   = (const float*)d_in[4];
    const float* dtw   = (const float*)d_in[5];
    const float* dtb   = (const float*)d_in[6];
    const float* A_log = (const float*)d_in[7];
    const float* Dvec  = (const float*)d_in[8];
    const float* opw   = (const float*)d_in[9];
    float* out = (float*)d_out;

    static int configured = 0;
    if (!configured) {
        cudaFuncSetAttribute(k_gemm1_mma, cudaFuncAttributeMaxDynamicSharedMemorySize, G1_SMEM);
        cudaFuncSetAttribute(k_gemm2_mma, cudaFuncAttributeMaxDynamicSharedMemorySize, G1_SMEM);
        cudaFuncSetAttribute(k_dt_mma,   cudaFuncAttributeMaxDynamicSharedMemorySize, G1_SMEM);
        configured = 1;
    }

    k_prep<<<PB_PATCH + PB_WSPLIT + PB_XPAD + PB_DTW + PB_COLSUM, 256>>>(
        x, w_in, xpw, dtw, opw);
    k_gemm1_mma<<<dim3(2 * DIN / 128, LSEQ / 128), 256, G1_SMEM>>>();
    k_conv<<<(LSEQ / 8) * (DIN / 4) / 256, 256>>>(convw, convb, Dvec);
    k_gemm2_mma<<<dim3(LSEQ / 128, G2_KSPLIT), 256, G1_SMEM>>>();
    k_g2red<<<(LSEQ * NCOL) / 256, 256>>>();
    k_dt_mma<<<dim3(LSEQ / 128, DIN / 128), 256, G1_SMEM>>>(dtb);
    k_scan1<<<dim3(DIN / 256, NCHUNK), 256>>>(A_log);
    k_scan2<<<96, 256>>>();
    k_final<<<1, 256>>>(out);
}

// round 17
// speedup vs baseline: 1.0738x; 1.0738x over previous
#include <cuda_runtime.h>
#include <cuda_bf16.h>
#include <cuda_fp16.h>
#include <math.h>
#include <stdint.h>

#define LSEQ 4096
#define DMOD 768
#define DIN  1536
#define DST  16
#define RNK  48
#define NCOL 80
#define NCHUNK 64
#define CHLEN  64
#define NLT    32                        // l-tiles (LSEQ/128)
#define INV_LM (1.0f / (4096.0f * 768.0f))

// ---------------- scratch ----------------------------------------------------
__device__ float d_wsum[DIN];
__device__ __half d_uh [LSEQ * DMOD];
__device__ __half d_wh [2 * DIN * DMOD];
__device__ __half d_xsh[LSEQ * DIN];
__device__ __half d_gh [LSEQ * DIN];     // g' = silu(z)*wsum  (INV_LM applied later)
__device__ __half d_xpwh[128 * DIN];     // padded x_proj_w (rows 80..127 = 0)
__device__ __half d_dbch[LSEQ * 64];     // dbc[:, :48] K-padded to 64
__device__ __half d_dtwh[DIN * 64];      // dt_proj_w K-padded to 64
__device__ float d_halo_lo[NLT][3][DIN]; // first 3 xz rows of each l-tile
__device__ float d_halo_hi[NLT][3][DIN]; // last 3 xz rows of each l-tile
__device__ float d_dt[LSEQ * DIN];
__device__ float d_dbc[LSEQ * NCOL];
#define G2_KSPLIT 8
__device__ float d_dbc_part[G2_KSPLIT][LSEQ * NCOL];
__device__ float d_P [NCHUNK * DIN * DST];
__device__ float d_E [NCHUNK * DIN * DST];
__device__ float d_Kc[NCHUNK * DIN * DST];
__device__ float d_part_scan[NCHUNK * 6];
__device__ float d_part_p2[96];

__device__ __forceinline__ float siluf(float x) { return x / (1.0f + __expf(-x)); }
__device__ __forceinline__ float softplusf(float s) {
    return (s > 20.0f) ? s : __logf(1.0f + __expf(s));
}

__device__ __forceinline__ float blockReduceSum(float v) {
    __shared__ float sh[32];
    int lane = threadIdx.x & 31;
    int w    = threadIdx.x >> 5;
    #pragma unroll
    for (int o = 16; o > 0; o >>= 1) v += __shfl_down_sync(0xffffffffu, v, o);
    if (lane == 0) sh[w] = v;
    __syncthreads();
    int nw = blockDim.x >> 5;
    v = (threadIdx.x < nw) ? sh[threadIdx.x] : 0.0f;
    if (w == 0) {
        #pragma unroll
        for (int o = 16; o > 0; o >>= 1) v += __shfl_down_sync(0xffffffffu, v, o);
    }
    return v;
}

// ---------------- asm helpers (sm_80-baseline) -------------------------------
__device__ __forceinline__ uint32_t smem_to_u32(const void* p) {
    uint32_t a;
    asm("{ .reg .u64 t; cvta.to.shared.u64 t, %1; cvt.u32.u64 %0, t; }" : "=r"(a) : "l"(p));
    return a;
}
#define CP16(sm, gp) \
    asm volatile("cp.async.cg.shared.global [%0], [%1], 16;" :: "r"(sm), "l"(gp))
#define CP_COMMIT() asm volatile("cp.async.commit_group;" ::: "memory")
#define CP_WAIT0()  asm volatile("cp.async.wait_group 0;" ::: "memory")
#define CP_WAIT1()  asm volatile("cp.async.wait_group 1;" ::: "memory")
#define CP_WAIT2()  asm volatile("cp.async.wait_group 2;" ::: "memory")

__device__ __forceinline__ void ldsm_x4(uint32_t& r0, uint32_t& r1, uint32_t& r2,
                                        uint32_t& r3, uint32_t addr) {
    asm volatile("ldmatrix.sync.aligned.m8n8.x4.shared.b16 {%0,%1,%2,%3}, [%4];"
                 : "=r"(r0), "=r"(r1), "=r"(r2), "=r"(r3) : "r"(addr));
}
__device__ __forceinline__ void mma16816(float* c, const uint32_t* a, const uint32_t* b) {
    asm volatile("mma.sync.aligned.m16n8k16.row.col.f32.f16.f16.f32 "
                 "{%0,%1,%2,%3}, {%4,%5,%6,%7}, {%8,%9}, {%0,%1,%2,%3};"
                 : "+f"(c[0]), "+f"(c[1]), "+f"(c[2]), "+f"(c[3])
                 : "r"(a[0]), "r"(a[1]), "r"(a[2]), "r"(a[3]), "r"(b[0]), "r"(b[1]));
}

// swizzled 64B-row addressing: row r, 16B slot s -> conflict-free ldmatrix
__device__ __forceinline__ uint32_t swz(uint32_t row, uint32_t slot) {
    return row * 64u + ((slot ^ ((row >> 1) & 3u)) << 4);
}

// ---------------- K_prep: patchT + wsplit + xpw pad + dtw pad + colsum -------
#define PB_PATCH  384
#define PB_WSPLIT ((2 * DIN * DMOD) / 256)       // 9216
#define PB_XPAD   ((128 * DIN) / 256)            // 768
#define PB_DTW    ((DIN * 64) / 256)             // 384
#define PB_COLSUM (DIN / 16)                     // 96
__global__ void k_prep(const float* __restrict__ x,
                       const float* __restrict__ w,
                       const float* __restrict__ xpw,
                       const float* __restrict__ dtw,
                       const float* __restrict__ opw) {
    __shared__ __half shp[8][1024];
    int bid = blockIdx.x;
    int t = threadIdx.x;
    if (bid < PB_PATCH) {
        int c   = bid >> 7;
        int rem = bid & 127;
        int ih0 = (rem >> 4) * 8;
        int a   = rem & 15;
        #pragma unroll
        for (int rep = 0; rep < 8; rep++) {
            int j    = t + rep * 256;
            int row  = j >> 8;
            int col4 = j & 255;
            int H = (ih0 + row) * 16 + a;
            float4 v = *(const float4*)&x[c * 1048576 + H * 1024 + col4 * 4];
            shp[row][col4 * 4 + 0] = __float2half(v.x);
            shp[row][col4 * 4 + 1] = __float2half(v.y);
            shp[row][col4 * 4 + 2] = __float2half(v.z);
            shp[row][col4 * 4 + 3] = __float2half(v.w);
        }
        __syncthreads();
        int iwr = t >> 4, b = t & 15;
        int l  = iwr * 256 + a * 16 + b;
        int d0 = c * 256 + ih0 * 4;
        int colbase = iwr * 16 + b;
        uint32_t hv[16];
        #pragma unroll
        for (int j = 0; j < 16; j++) {
            int d2 = 2 * j;
            int i0 = d2 >> 2,       q0 = d2 & 3;
            int i1 = (d2 + 1) >> 2, q1 = (d2 + 1) & 3;
            __half2 hp = {shp[i0][q0 * 256 + colbase], shp[i1][q1 * 256 + colbase]};
            hv[j] = *(uint32_t*)&hp;
        }
        long base = (long)l * DMOD + d0;
        #pragma unroll
        for (int j = 0; j < 4; j++) {
            uint4 qh = {hv[4 * j], hv[4 * j + 1], hv[4 * j + 2], hv[4 * j + 3]};
            *(uint4*)&d_uh[base + j * 8] = qh;
        }
    } else if (bid < PB_PATCH + PB_WSPLIT) {
        int idx = (bid - PB_PATCH) * 256 + t;
        d_wh[idx] = __float2half(w[idx]);
    } else if (bid < PB_PATCH + PB_WSPLIT + PB_XPAD) {
        int idx = (bid - PB_PATCH - PB_WSPLIT) * 256 + t;
        int row = idx / DIN;
        d_xpwh[idx] = __float2half((row < NCOL) ? xpw[idx] : 0.0f);
    } else if (bid < PB_PATCH + PB_WSPLIT + PB_XPAD + PB_DTW) {
        int idx = (bid - PB_PATCH - PB_WSPLIT - PB_XPAD) * 256 + t;
        int row = idx >> 6;
        int k   = idx & 63;
        d_dtwh[idx] = __float2half((k < RNK) ? dtw[row * RNK + k] : 0.0f);
    } else {
        int cb = bid - PB_PATCH - PB_WSPLIT - PB_XPAD - PB_DTW;
        __shared__ float shc[16][17];
        int dl = t & 15;
        int mg = t >> 4;
        int d  = cb * 16 + dl;
        float s = 0.0f;
        for (int m = mg * 48; m < mg * 48 + 48; m++) s += opw[m * DIN + d];
        shc[dl][mg] = s;
        __syncthreads();
        if (t < 16) {
            float tot = 0.0f;
            #pragma unroll
            for (int g = 0; g < 16; g++) tot += shc[t][g];
            d_wsum[cb * 16 + t] = tot;
        }
    }
}

// ---------------- shared GEMM machinery (fp16, single term, 4-stage) ---------
#define G1_TILE   8192                  // 128 rows * 64 B
#define G1_STAGE  (2 * G1_TILE)         // A, B = 16384 B
#define G1_NSTG   4
#define G1_SMEM   66560                 // max(4*16384, 128*130*4) = 66560
#define G1_ITERS  24                    // 768 / 32

__device__ __forceinline__ void gx_prefetch(
        uint32_t sbase, int stage, int k0, int l0, int n0, int t,
        const __half* A, const __half* B, int kstride) {
    const uint32_t so = sbase + stage * G1_STAGE;
    const int prow = t >> 2;
    const int pq   = t & 3;
    #pragma unroll
    for (int rep = 0; rep < 2; rep++) {
        int row = prow + rep * 64;
        uint32_t soff = swz((uint32_t)row, (uint32_t)pq);
        long ga = (long)(l0 + row) * kstride + k0 + pq * 8;
        long gb = (long)(n0 + row) * kstride + k0 + pq * 8;
        CP16(so + soff,           (const void*)(A + ga));
        CP16(so + G1_TILE + soff, (const void*)(B + gb));
    }
}

__device__ __forceinline__ void gx_mainloop_iter(uint32_t so, int lane, int wm, int wn,
                                                 float acc[4][4][4]) {
    #pragma unroll
    for (int kk = 0; kk < 2; kk++) {
        const uint32_t arow = (uint32_t)(wm * 64 + (lane & 15));
        const uint32_t aslot = (uint32_t)(kk * 2 + (lane >> 4));
        const int g = lane >> 3;
        const uint32_t brow = (uint32_t)(wn * 32 + ((g >> 1) << 3) + (lane & 7));
        const uint32_t bslot = (uint32_t)(kk * 2 + (g & 1));

        uint32_t af[4][4];
        #pragma unroll
        for (int mt = 0; mt < 4; mt++) {
            uint32_t addr = so + swz(arow + mt * 16, aslot);
            ldsm_x4(af[mt][0], af[mt][1], af[mt][2], af[mt][3], addr);
        }
        uint32_t bf[4][2];
        #pragma unroll
        for (int np = 0; np < 2; np++) {
            uint32_t addr = so + G1_TILE + swz(brow + np * 16, bslot);
            ldsm_x4(bf[2 * np][0], bf[2 * np][1],
                    bf[2 * np + 1][0], bf[2 * np + 1][1], addr);
        }
        #pragma unroll
        for (int mt = 0; mt < 4; mt++)
            #pragma unroll
            for (int nt = 0; nt < 4; nt++)
                mma16816(acc[mt][nt], af[mt], bf[nt]);
    }
}

// ---------------- K2: GEMM1 + fused conv/silu epilogue -----------------------
// x-half (n0 < DIN): stage acc to smem, run depthwise conv(4)+silu for rows
// l0+3..l0+127 (halo rows handled by k_fixup), emit xsh fp16. Store 3-row
// halos. z-half: g' = silu(z)*wsum fp16.
__global__ void __launch_bounds__(256, 2) k_gemm1_mma(const float* __restrict__ convw,
                                                      const float* __restrict__ convb) {
    extern __shared__ char smem[];
    const uint32_t sbase = smem_to_u32(smem);
    const int t    = threadIdx.x;
    const int lane = t & 31;
    const int wid  = t >> 5;
    const int wm   = wid >> 2;
    const int wn   = wid & 3;
    const int n0   = blockIdx.x * 128;
    const int l0   = blockIdx.y * 128;

    float acc[4][4][4];
    #pragma unroll
    for (int i = 0; i < 4; i++)
        #pragma unroll
        for (int j = 0; j < 4; j++)
            #pragma unroll
            for (int q = 0; q < 4; q++) acc[i][j][q] = 0.0f;

    #pragma unroll
    for (int s = 0; s < 3; s++) {
        gx_prefetch(sbase, s, s * 32, l0, n0, t, d_uh, d_wh, DMOD);
        CP_COMMIT();
    }

    for (int c = 0; c < G1_ITERS; c++) {
        CP_WAIT2();
        __syncthreads();
        if (c + 3 < G1_ITERS)
            gx_prefetch(sbase, (c + 3) % G1_NSTG, (c + 3) * 32, l0, n0, t,
                        d_uh, d_wh, DMOD);
        CP_COMMIT();
        gx_mainloop_iter(sbase + (c % G1_NSTG) * G1_STAGE, lane, wm, wn, acc);
    }

    if (n0 < DIN) {
        // ---- stage acc into smem [128][130] fp32 ----
        float* sst = (float*)smem;
        CP_WAIT0();
        __syncthreads();          // all pipeline smem reads done
        #pragma unroll
        for (int mt = 0; mt < 4; mt++) {
            int rl = wm * 64 + mt * 16 + (lane >> 2);
            #pragma unroll
            for (int nt = 0; nt < 4; nt++) {
                int cl = wn * 32 + nt * 8 + 2 * (lane & 3);
                float2 v0 = {acc[mt][nt][0], acc[mt][nt][1]};
                float2 v1 = {acc[mt][nt][2], acc[mt][nt][3]};
                *(float2*)&sst[rl * 130 + cl]       = v0;
                *(float2*)&sst[(rl + 8) * 130 + cl] = v1;
            }
        }
        __syncthreads();
        const int tile = l0 >> 7;
        // ---- halo stores (first 3 + last 3 rows) ----
        for (int idx = t; idx < 384; idx += 256) {
            int row = idx >> 7, col = idx & 127;
            d_halo_lo[tile][row][n0 + col] = sst[row * 130 + col];
            d_halo_hi[tile][row][n0 + col] = sst[(125 + row) * 130 + col];
        }
        // ---- conv+silu for rows 3..127 ----
        int col = t & 127;
        int ch  = n0 + col;
        float4 wv = *(const float4*)&convw[ch * 4];
        float bia = convb[ch];
        for (int r = 3 + (t >> 7); r < 128; r += 2) {
            float s = bia + wv.x * sst[(r - 3) * 130 + col]
                          + wv.y * sst[(r - 2) * 130 + col]
                          + wv.z * sst[(r - 1) * 130 + col]
                          + wv.w * sst[r * 130 + col];
            d_xsh[(long)(l0 + r) * DIN + ch] = __float2half(siluf(s));
        }
    } else {
        // z-half: g' = silu(z) * wsum   (NO INV_LM here — fp16 subnormal hazard)
        const int zb = n0 - DIN;
        #pragma unroll
        for (int mt = 0; mt < 4; mt++) {
            int r0 = l0 + wm * 64 + mt * 16 + (lane >> 2);
            #pragma unroll
            for (int nt = 0; nt < 4; nt++) {
                int cc = zb + wn * 32 + nt * 8 + 2 * (lane & 3);
                float w0 = d_wsum[cc];
                float w1 = d_wsum[cc + 1];
                __half2 g0 = __floats2half2_rn(siluf(acc[mt][nt][0]) * w0,
                                               siluf(acc[mt][nt][1]) * w1);
                __half2 g1 = __floats2half2_rn(siluf(acc[mt][nt][2]) * w0,
                                               siluf(acc[mt][nt][3]) * w1);
                *(uint32_t*)&d_gh[(long)r0 * DIN + cc]       = *(uint32_t*)&g0;
                *(uint32_t*)&d_gh[(long)(r0 + 8) * DIN + cc] = *(uint32_t*)&g1;
            }
        }
    }
}

// ---------------- K_fixup: conv for the 3 boundary rows of each l-tile -------
__global__ void k_fixup(const float* __restrict__ convw,
                        const float* __restrict__ convb) {
    int idx = blockIdx.x * 256 + threadIdx.x;   // < NLT*3*DIN
    int ti  = idx / (3 * DIN);
    int rem = idx - ti * 3 * DIN;
    int j   = rem / DIN;
    int ch  = rem - j * DIN;
    int l   = ti * 128 + j;
    float s = convb[ch];
    #pragma unroll
    for (int k = 0; k < 4; k++) {
        int r = l - 3 + k;
        float v = 0.0f;
        if (r >= 0) {
            int tb = r >> 7, ro = r & 127;
            v = (tb == ti) ? d_halo_lo[ti][ro][ch]
                           : d_halo_hi[tb][ro - 125][ch];
        }
        s += convw[ch * 4 + k] * v;
    }
    d_xsh[(long)l * DIN + ch] = __float2half(siluf(s));
}

// ---------------- K4: GEMM2 via mma.sync, split-K 8 --------------------------
#define G2_KLEN  (DIN / G2_KSPLIT)     // 192
#define G2_ITERS (G2_KLEN / 32)        // 6
__global__ void __launch_bounds__(256, 2) k_gemm2_mma() {
    extern __shared__ char smem[];
    const uint32_t sbase = smem_to_u32(smem);
    const int t    = threadIdx.x;
    const int lane = t & 31;
    const int wid  = t >> 5;
    const int wm   = wid >> 2;
    const int wn   = wid & 3;
    const int l0   = blockIdx.x * 128;
    const int kz   = blockIdx.y;
    const int kbase = kz * G2_KLEN;

    float acc[4][4][4];
    #pragma unroll
    for (int i = 0; i < 4; i++)
        #pragma unroll
        for (int j = 0; j < 4; j++)
            #pragma unroll
            for (int q = 0; q < 4; q++) acc[i][j][q] = 0.0f;

    #pragma unroll
    for (int s = 0; s < 3; s++) {
        gx_prefetch(sbase, s, kbase + s * 32, l0, 0, t, d_xsh, d_xpwh, DIN);
        CP_COMMIT();
    }

    for (int c = 0; c < G2_ITERS; c++) {
        CP_WAIT2();
        __syncthreads();
        if (c + 3 < G2_ITERS)
            gx_prefetch(sbase, (c + 3) % G1_NSTG, kbase + (c + 3) * 32, l0, 0, t,
                        d_xsh, d_xpwh, DIN);
        CP_COMMIT();
        gx_mainloop_iter(sbase + (c % G1_NSTG) * G1_STAGE, lane, wm, wn, acc);
    }

    #pragma unroll
    for (int mt = 0; mt < 4; mt++) {
        int r0 = l0 + wm * 64 + mt * 16 + (lane >> 2);
        #pragma unroll
        for (int nt = 0; nt < 4; nt++) {
            int cc = wn * 32 + nt * 8 + 2 * (lane & 3);
            if (cc + 1 < NCOL) {
                float2 v0 = {acc[mt][nt][0], acc[mt][nt][1]};
                float2 v1 = {acc[mt][nt][2], acc[mt][nt][3]};
                *(float2*)&d_dbc_part[kz][(long)r0 * NCOL + cc]       = v0;
                *(float2*)&d_dbc_part[kz][(long)(r0 + 8) * NCOL + cc] = v1;
            }
        }
    }
}

// ---------------- K4b: reduce split-K partials + emit dbc fp16 ---------------
__global__ void k_g2red() {
    int idx = blockIdx.x * 256 + threadIdx.x;   // < LSEQ*NCOL
    float s = 0.0f;
    #pragma unroll
    for (int kz = 0; kz < G2_KSPLIT; kz++) s += d_dbc_part[kz][idx];
    d_dbc[idx] = s;
    int l   = idx / NCOL;
    int col = idx - l * NCOL;
    if (col < RNK) {
        d_dbch[l * 64 + col] = __float2half(s);
    } else if (col >= 64) {
        d_dbch[l * 64 + col - 16] = __float2half(0.0f);
    }
}

// ---------------- K5: dt via mma.sync (M=4096, N=1536, K=48->64) -------------
__global__ void __launch_bounds__(256, 2) k_dt_mma(const float* __restrict__ dtb) {
    extern __shared__ char smem[];
    const uint32_t sbase = smem_to_u32(smem);
    const int t    = threadIdx.x;
    const int lane = t & 31;
    const int wid  = t >> 5;
    const int wm   = wid >> 2;
    const int wn   = wid & 3;
    const int l0   = blockIdx.x * 128;
    const int n0   = blockIdx.y * 128;

    float acc[4][4][4];
    #pragma unroll
    for (int i = 0; i < 4; i++)
        #pragma unroll
        for (int j = 0; j < 4; j++)
            #pragma unroll
            for (int q = 0; q < 4; q++) acc[i][j][q] = 0.0f;

    gx_prefetch(sbase, 0, 0, l0, n0, t, d_dbch, d_dtwh, 64);
    CP_COMMIT();
    gx_prefetch(sbase, 1, 32, l0, n0, t, d_dbch, d_dtwh, 64);
    CP_COMMIT();

    CP_WAIT1();
    __syncthreads();
    gx_mainloop_iter(sbase, lane, wm, wn, acc);
    CP_WAIT0();
    __syncthreads();
    gx_mainloop_iter(sbase + G1_STAGE, lane, wm, wn, acc);

    #pragma unroll
    for (int mt = 0; mt < 4; mt++) {
        int r0 = l0 + wm * 64 + mt * 16 + (lane >> 2);
        #pragma unroll
        for (int nt = 0; nt < 4; nt++) {
            int cc = n0 + wn * 32 + nt * 8 + 2 * (lane & 3);
            float b0 = dtb[cc], b1 = dtb[cc + 1];
            float2 v0 = {softplusf(acc[mt][nt][0] + b0), softplusf(acc[mt][nt][1] + b1)};
            float2 v1 = {softplusf(acc[mt][nt][2] + b0), softplusf(acc[mt][nt][3] + b1)};
            *(float2*)&d_dt[(long)r0 * DIN + cc]       = v0;
            *(float2*)&d_dt[(long)(r0 + 8) * DIN + cc] = v1;
        }
    }
}

// ---------------- K6: scan pass 1 (now also accumulates xs*D*g term) ---------
__global__ void k_scan1(const float* __restrict__ A_log,
                        const float* __restrict__ Dvec) {
    __shared__ __align__(16) float sB[CHLEN][DST];
    __shared__ __align__(16) float sC[CHLEN][DST];
    int t = threadIdx.x;
    int d = blockIdx.x * 256 + t;
    int c = blockIdx.y;
    int base = c * CHLEN;
    for (int p = t; p < CHLEN * DST; p += 256) {
        int r = p >> 4, s = p & 15;
        sB[r][s] = d_dbc[(base + r) * NCOL + RNK + s];
        sC[r][s] = d_dbc[(base + r) * NCOL + RNK + DST + s];
    }
    __syncthreads();

    float Av[DST];
    #pragma unroll
    for (int s = 0; s < DST; s++) Av[s] = -__expf(A_log[d * DST + s]);
    bool fast = true;
    #pragma unroll
    for (int s = 1; s < DST; s++) {
        float r = Av[s] / Av[0];
        fast = fast && (fabsf(r - (float)(s + 1)) < 1e-3f);
    }
    float Dv = Dvec[d];

    float h[DST], cp[DST], K[DST];
    #pragma unroll
    for (int s = 0; s < DST; s++) { h[s] = 0.0f; cp[s] = 1.0f; K[s] = 0.0f; }
    float acc = 0.0f;

    for (int i = 0; i < CHLEN; i++) {
        int l = base + i;
        float dtv = d_dt[(long)l * DIN + d];
        float xsv = __half2float(d_xsh[(long)l * DIN + d]);
        float gv  = __half2float(d_gh [(long)l * DIN + d]) * INV_LM;
        float dtx = dtv * xsv;
        acc += xsv * Dv * gv;               // fused D-term (was in k_conv)
        float dAv[DST];
        if (fast) {
            float E  = __expf(dtv * Av[0]);
            float p2 = E * E, p4 = p2 * p2, p8 = p4 * p4;
            dAv[0] = E;        dAv[1] = p2;       dAv[2] = p2 * E;
            dAv[3] = p4;       dAv[4] = p4 * E;   dAv[5] = p4 * p2;
            dAv[6] = p4 * dAv[2]; dAv[7] = p8;
            dAv[8] = p8 * E;   dAv[9] = p8 * p2;  dAv[10] = p8 * dAv[2];
            dAv[11] = p8 * p4; dAv[12] = p8 * dAv[4]; dAv[13] = p8 * dAv[5];
            dAv[14] = p8 * dAv[6]; dAv[15] = p8 * p8;
        } else {
            #pragma unroll
            for (int s = 0; s < DST; s++) dAv[s] = __expf(dtv * Av[s]);
        }
        #pragma unroll
        for (int s = 0; s < DST; s++) {
            float dA = dAv[s];
            cp[s] *= dA;
            h[s] = dA * h[s] + dtx * sB[i][s];
            float cg = sC[i][s] * gv;
            acc  += h[s] * cg;
            K[s] += cp[s] * cg;
        }
    }
    long off = ((long)c * DIN + d) * DST;
    #pragma unroll
    for (int s = 0; s < DST; s++) {
        d_P [off + s] = cp[s];
        d_E [off + s] = h[s];
        d_Kc[off + s] = K[s];
    }
    float tot = blockReduceSum(acc);
    if (t == 0) d_part_scan[c * 6 + blockIdx.x] = tot;
}

// ---------------- K7: scan pass 2 (chunk combine) ----------------------------
__global__ void k_scan2() {
    int gid = blockIdx.x * 256 + threadIdx.x;
    float h = 0.0f, St = 0.0f;
    for (int c = 0; c < NCHUNK; c++) {
        long off = (long)c * (DIN * DST) + gid;
        St += d_Kc[off] * h;
        h   = d_P[off] * h + d_E[off];
    }
    float tot = blockReduceSum(St);
    if (threadIdx.x == 0) d_part_p2[blockIdx.x] = tot;
}

// ---------------- K8: deterministic final reduce -----------------------------
__global__ void k_final(float* __restrict__ out) {
    int t = threadIdx.x;
    float v = 0.0f;
    for (int i = t; i < NCHUNK * 6; i += 256)    v += d_part_scan[i];
    for (int i = t; i < 96; i += 256)            v += d_part_p2[i];
    float tot = blockReduceSum(v);
    if (t == 0) out[0] = tot;
}

// ---------------- launch -----------------------------------------------------
extern "C" void kernel_launch(void* const* d_in, const int* in_sizes, int n_in,
                              void* d_out, int out_size) {
    const float* x     = (const float*)d_in[0];
    const float* w_in  = (const float*)d_in[1];
    const float* convw = (const float*)d_in[2];
    const float* convb = (const float*)d_in[3];
    const float* xpw   = (const float*)d_in[4];
    const float* dtw   = (const float*)d_in[5];
    const float* dtb   = (const float*)d_in[6];
    const float* A_log = (const float*)d_in[7];
    const float* Dvec  = (const float*)d_in[8];
    const float* opw   = (const float*)d_in[9];
    float* out = (float*)d_out;

    static int configured = 0;
    if (!configured) {
        cudaFuncSetAttribute(k_gemm1_mma, cudaFuncAttributeMaxDynamicSharedMemorySize, G1_SMEM);
        cudaFuncSetAttribute(k_gemm2_mma, cudaFuncAttributeMaxDynamicSharedMemorySize, G1_SMEM);
        cudaFuncSetAttribute(k_dt_mma,   cudaFuncAttributeMaxDynamicSharedMemorySize, G1_SMEM);
        configured = 1;
    }

    k_prep<<<PB_PATCH + PB_WSPLIT + PB_XPAD + PB_DTW + PB_COLSUM, 256>>>(
        x, w_in, xpw, dtw, opw);
    k_gemm1_mma<<<dim3(2 * DIN / 128, LSEQ / 128), 256, G1_SMEM>>>(convw, convb);
    k_fixup<<<(NLT * 3 * DIN) / 256, 256>>>(convw, convb);
    k_gemm2_mma<<<dim3(LSEQ / 128, G2_KSPLIT), 256, G1_SMEM>>>();
    k_g2red<<<(LSEQ * NCOL) / 256, 256>>>();
    k_dt_mma<<<dim3(LSEQ / 128, DIN / 128), 256, G1_SMEM>>>(dtb);
    k_scan1<<<dim3(DIN / 256, NCHUNK), 256>>>(A_log, Dvec);
    k_scan2<<<96, 256>>>();
    k_final<<<1, 256>>>(out);
}